// round 4
// baseline (speedup 1.0000x reference)
#include <cuda_runtime.h>
#include <cstdint>

// Problem constants (D=20, RANK=2 -> o=19 per axis, m=32)
#define O      19
#define DM     20
#define MM     32
#define ROWP   36                    // padded row -> conflict-free LDS.128
#define CT_STRIDE (MM*ROWP)          // 1152 floats per cos-table slab
#define NT     640                   // 20 warps: (c-pair 0..9) x (d-group 0..1)
#define NITEMS (O*O*2)               // (a,b) x d-half

typedef unsigned long long ull;

// ---- packed f32x2 helpers ----
__device__ __forceinline__ ull f2mul(ull a, ull b) {
    ull r; asm("mul.rn.f32x2 %0, %1, %2;" : "=l"(r) : "l"(a), "l"(b)); return r;
}
__device__ __forceinline__ ull f2fma(ull a, ull b, ull c) {
    ull r; asm("fma.rn.f32x2 %0, %1, %2, %3;" : "=l"(r) : "l"(a), "l"(b), "l"(c)); return r;
}
__device__ __forceinline__ float f2sum(ull v) {
    return __uint_as_float((unsigned)v) + __uint_as_float((unsigned)(v >> 32));
}

// Shared memory layout (floats):
//   Ct  [19][32][36] @ 0      (21888)  Ct[n][i][j] = cos(2*pi*n/(32*i+j+2))
//   R   [20][20][32] @ 21888  (12800)  (a,b)-pair sum of hypervol
//   Gab [32][36]     @ 34688  (1152)   P * Ct[A] * Ct[B]
//   Msc [32][36]     @ 35840  (1152)   M_w / 16
//   WS  [190][32]    @ 36992  (6080)   2x2x2x2 window sums (c*10+dd slots)
//   X   [190][32]    @ 43072  (6080)   x[c*10+dd, j]
#define CT_OFF   0
#define R_OFF    21888
#define GAB_OFF  34688
#define MS_OFF   35840
#define WS_OFF   36992
#define X_OFF    43072
#define SMEM_FLOATS 49152
#define SMEM_BYTES (SMEM_FLOATS * 4)

__global__ void __launch_bounds__(NT, 1)
pm4_kernel(const float* __restrict__ H,   // [20,20,20,20,32]
           const float* __restrict__ Mw,  // [32,32]
           const float* __restrict__ P,   // [32,32]
           float* __restrict__ out)       // [19^4, 32]
{
    extern __shared__ float s[];
    float* Ct  = s + CT_OFF;
    float* R   = s + R_OFF;
    float* Gab = s + GAB_OFF;
    float* Msc = s + MS_OFF;
    float* WS  = s + WS_OFF;
    float* X   = s + X_OFF;

    const int tid  = threadIdx.x;
    const int lane = tid & 31;
    const int w    = tid >> 5;
    const int cp   = w >> 1;          // 0..9
    const int dg   = w & 1;           // 0..1
    const int c0   = 2 * cp;
    const int nc   = (cp == 9) ? 1 : 2;
    const int c1   = (nc == 2) ? c0 + 1 : c0;
    const int g    = gridDim.x;

    const float TWO_PI = 6.28318530717958647692f;

    // ---- once per CTA: cos table + prescaled M ----
    for (int e = tid; e < O * MM * MM; e += NT) {
        int n = e >> 10;
        int r = e & 1023;
        int i = r >> 5;
        int j = r & 31;
        float per = (float)(i * MM + j + 2);
        Ct[n * CT_STRIDE + i * ROWP + j] = cosf(TWO_PI * (float)n / per);
    }
    for (int e = tid; e < MM * MM; e += NT) {
        Msc[(e >> 5) * ROWP + (e & 31)] = Mw[e] * 0.0625f;
    }

    for (int item = blockIdx.x; item < NITEMS; item += g) {
        const int ab = item >> 1;
        const int dh = item & 1;
        const int A = ab / O;
        const int B = ab % O;
        const int dstart = dh ? 10 : 0;
        const int dnum   = dh ? 9 : 10;

        __syncthreads();   // prior item fully consumed; Ct/Msc ready (first iter)

        // ---- R = 2x2 (a,b) pair-sum, float4 contiguous ----
        {
            const int strideB = DM * DM * MM;        // 12800 floats
            const int strideA = DM * strideB;
            const float4* H00 = (const float4*)(H + (long)A * strideA + (long)B * strideB);
            const float4* H01 = H00 + strideB / 4;
            const float4* H10 = H00 + strideA / 4;
            const float4* H11 = H10 + strideB / 4;
            float4* R4 = (float4*)R;
            #pragma unroll 1
            for (int e = tid; e < DM * DM * MM / 4; e += NT) {
                float4 a = H00[e], b = H01[e], c = H10[e], d4 = H11[e];
                R4[e] = make_float4(a.x + b.x + c.x + d4.x, a.y + b.y + c.y + d4.y,
                                    a.z + b.z + c.z + d4.z, a.w + b.w + c.w + d4.w);
            }
        }
        // ---- Gab = P * Ct[A] * Ct[B] (cooperative) ----
        for (int e = tid; e < MM * MM; e += NT) {
            int i = e >> 5, j = e & 31;
            Gab[i * ROWP + j] = P[e] * Ct[A * CT_STRIDE + i * ROWP + j]
                                     * Ct[B * CT_STRIDE + i * ROWP + j];
        }
        __syncthreads();   // R, Gab ready

        // ---- Phase P-a: all 2x2 window sums -> WS (no intra-warp sync) ----
        #pragma unroll 1
        for (int e = tid; e < O * 10 * 32; e += NT) {
            int l = e & 31;
            int p = e >> 5;            // c*10 + dd
            int c = p / 10;
            int dd = p - c * 10;
            if (dd < dnum) {
                int d = dstart + dd;
                const float* r0 = &R[(c * DM + d) * MM + l];
                WS[p * 32 + l] = (r0[0] + r0[MM]) + (r0[DM * MM] + r0[DM * MM + MM]);
            }
        }
        __syncthreads();   // WS ready

        // ---- Phase P-b: matvec x = (M/16) * ws  (lane = j, broadcast WS rows) ----
        {
            ull Mreg[16];
            #pragma unroll
            for (int l4 = 0; l4 < 8; l4++) {
                ulonglong2 m = *reinterpret_cast<const ulonglong2*>(&Msc[lane * ROWP + 4 * l4]);
                Mreg[2 * l4] = m.x; Mreg[2 * l4 + 1] = m.y;
            }
            #pragma unroll 1
            for (int p = w; p < O * 10; p += 20) {
                int c = p / 10;
                int dd = p - c * 10;
                if (dd < dnum) {
                    const float* wsrow = &WS[p * 32];
                    ull a0 = 0, a1 = 0;
                    #pragma unroll
                    for (int l4 = 0; l4 < 8; l4++) {
                        ulonglong2 wv = *reinterpret_cast<const ulonglong2*>(wsrow + 4 * l4);
                        a0 = f2fma(Mreg[2 * l4],     wv.x, a0);
                        a1 = f2fma(Mreg[2 * l4 + 1], wv.y, a1);
                    }
                    X[p * 32 + lane] = f2sum(a0) + f2sum(a1);
                }
            }
        }

        // ---- per-warp G fold: G = Gab * Ct[c] in registers ----
        ull G0[16], G1[16];
        #pragma unroll
        for (int l4 = 0; l4 < 8; l4++) {
            ulonglong2 gv = *reinterpret_cast<const ulonglong2*>(&Gab[lane * ROWP + 4 * l4]);
            ulonglong2 ca = *reinterpret_cast<const ulonglong2*>(&Ct[c0 * CT_STRIDE + lane * ROWP + 4 * l4]);
            ulonglong2 cb = *reinterpret_cast<const ulonglong2*>(&Ct[c1 * CT_STRIDE + lane * ROWP + 4 * l4]);
            G0[2 * l4]     = f2mul(gv.x, ca.x);
            G0[2 * l4 + 1] = f2mul(gv.y, ca.y);
            G1[2 * l4]     = f2mul(gv.x, cb.x);
            G1[2 * l4 + 1] = f2mul(gv.y, cb.y);
        }
        __syncthreads();   // X ready

        // ---- Phase C: warp = (c-pair, d-group), lane = i; dd unrolled x2 ----
        const int outBase = ab * (O * O) * MM;
        int dd = dg;
        for (; dd + 2 < dnum; dd += 4) {
            const int d0 = dstart + dd, d1 = dstart + dd + 2;
            const float* cr0 = &Ct[d0 * CT_STRIDE + lane * ROWP];
            const float* cr1 = &Ct[d1 * CT_STRIDE + lane * ROWP];
            const float* x00 = &X[(c0 * 10 + dd) * 32];
            const float* x01 = &X[(c0 * 10 + dd + 2) * 32];
            const float* x10 = &X[(c1 * 10 + dd) * 32];
            const float* x11 = &X[(c1 * 10 + dd + 2) * 32];
            ull a00 = 0, a01 = 0, a10 = 0, a11 = 0;
            #pragma unroll
            for (int l4 = 0; l4 < 8; l4++) {
                ulonglong2 cd0 = *reinterpret_cast<const ulonglong2*>(cr0 + 4 * l4);
                ulonglong2 cd1 = *reinterpret_cast<const ulonglong2*>(cr1 + 4 * l4);
                ulonglong2 v00 = *reinterpret_cast<const ulonglong2*>(x00 + 4 * l4);
                ulonglong2 v01 = *reinterpret_cast<const ulonglong2*>(x01 + 4 * l4);
                ulonglong2 v10 = *reinterpret_cast<const ulonglong2*>(x10 + 4 * l4);
                ulonglong2 v11 = *reinterpret_cast<const ulonglong2*>(x11 + 4 * l4);
                a00 = f2fma(f2mul(cd0.x, G0[2 * l4]),     v00.x, a00);
                a01 = f2fma(f2mul(cd1.x, G0[2 * l4]),     v01.x, a01);
                a10 = f2fma(f2mul(cd0.x, G1[2 * l4]),     v10.x, a10);
                a11 = f2fma(f2mul(cd1.x, G1[2 * l4]),     v11.x, a11);
                a00 = f2fma(f2mul(cd0.y, G0[2 * l4 + 1]), v00.y, a00);
                a01 = f2fma(f2mul(cd1.y, G0[2 * l4 + 1]), v01.y, a01);
                a10 = f2fma(f2mul(cd0.y, G1[2 * l4 + 1]), v10.y, a10);
                a11 = f2fma(f2mul(cd1.y, G1[2 * l4 + 1]), v11.y, a11);
            }
            out[outBase + (c0 * O + d0) * MM + lane] = f2sum(a00);
            out[outBase + (c0 * O + d1) * MM + lane] = f2sum(a01);
            if (nc == 2) {
                out[outBase + (c1 * O + d0) * MM + lane] = f2sum(a10);
                out[outBase + (c1 * O + d1) * MM + lane] = f2sum(a11);
            }
        }
        if (dd < dnum) {
            const int d0 = dstart + dd;
            const float* cr0 = &Ct[d0 * CT_STRIDE + lane * ROWP];
            const float* x00 = &X[(c0 * 10 + dd) * 32];
            const float* x10 = &X[(c1 * 10 + dd) * 32];
            ull a00 = 0, a00b = 0, a10 = 0, a10b = 0;
            #pragma unroll
            for (int l4 = 0; l4 < 8; l4++) {
                ulonglong2 cd0 = *reinterpret_cast<const ulonglong2*>(cr0 + 4 * l4);
                ulonglong2 v00 = *reinterpret_cast<const ulonglong2*>(x00 + 4 * l4);
                ulonglong2 v10 = *reinterpret_cast<const ulonglong2*>(x10 + 4 * l4);
                a00  = f2fma(f2mul(cd0.x, G0[2 * l4]),     v00.x, a00);
                a00b = f2fma(f2mul(cd0.y, G0[2 * l4 + 1]), v00.y, a00b);
                a10  = f2fma(f2mul(cd0.x, G1[2 * l4]),     v10.x, a10);
                a10b = f2fma(f2mul(cd0.y, G1[2 * l4 + 1]), v10.y, a10b);
            }
            out[outBase + (c0 * O + d0) * MM + lane] = f2sum(a00) + f2sum(a00b);
            if (nc == 2)
                out[outBase + (c1 * O + d0) * MM + lane] = f2sum(a10) + f2sum(a10b);
        }
    }
}

extern "C" void kernel_launch(void* const* d_in, const int* in_sizes, int n_in,
                              void* d_out, int out_size)
{
    const float* H  = (const float*)d_in[0];
    const float* Mw = (const float*)d_in[1];
    const float* P  = (const float*)d_in[2];
    float* out = (float*)d_out;

    cudaFuncSetAttribute(pm4_kernel, cudaFuncAttributeMaxDynamicSharedMemorySize, SMEM_BYTES);

    int dev = 0, nsm = 148;
    cudaGetDevice(&dev);
    cudaDeviceGetAttribute(&nsm, cudaDevAttrMultiProcessorCount, dev);
    if (nsm <= 0) nsm = 148;
    int grid = nsm > NITEMS ? NITEMS : nsm;

    pm4_kernel<<<grid, NT, SMEM_BYTES>>>(H, Mw, P, out);
}

// round 5
// speedup vs baseline: 1.7832x; 1.7832x over previous
#include <cuda_runtime.h>
#include <cstdint>

// Problem constants (D=20, RANK=2 -> o=19 per axis, m=32)
#define O      19
#define DM     20
#define MM     32
#define ROWP   36                    // padded row (floats) -> conflict-free LDS.128
#define CT_STRIDE (MM*ROWP)          // 1152 floats per cos-table slab
#define NT     640                   // 20 warps: (c-pair 0..9) x (d-group 0..1)
#define NITEMS (O*O*2)               // (a,b) x d-half

typedef unsigned long long ull;

// ---- packed f32x2 helpers ----
__device__ __forceinline__ ull f2mul(ull a, ull b) {
    ull r; asm("mul.rn.f32x2 %0, %1, %2;" : "=l"(r) : "l"(a), "l"(b)); return r;
}
__device__ __forceinline__ ull f2fma(ull a, ull b, ull c) {
    ull r; asm("fma.rn.f32x2 %0, %1, %2, %3;" : "=l"(r) : "l"(a), "l"(b), "l"(c)); return r;
}
__device__ __forceinline__ float f2sum(ull v) {
    return __uint_as_float((unsigned)v) + __uint_as_float((unsigned)(v >> 32));
}

// Shared memory layout (floats):
//   Ct  [19][32][36] @ 0      (21888)  Ct[n][i][j] = cos(2*pi*n / (32*i+j+2))
//   R   [20][20][32] @ 21888  (12800)  (a,b)-pair sum of hypervol
//   Gab [32][36]     @ 34688  (1152)   P * Ct[A] * Ct[B]
//   Msc [32][36]     @ 35840  (1152)   M_w / 16 (row-padded)
//   X   [19][10][32] @ 36992  (6080)   x[c, d-dstart, j] for current item
//   WS  [20][32]     @ 43072  (640)    per-warp window-sum staging
#define CT_OFF   0
#define R_OFF    21888
#define GAB_OFF  34688
#define MS_OFF   35840
#define X_OFF    36992
#define WS_OFF   43072
#define SMEM_FLOATS 43712
#define SMEM_BYTES (SMEM_FLOATS * 4)

__global__ void __launch_bounds__(NT, 1)
pm4_kernel(const float* __restrict__ H,   // [20,20,20,20,32]
           const float* __restrict__ Mw,  // [32,32]
           const float* __restrict__ P,   // [32,32]
           float* __restrict__ out)       // [19^4, 32]
{
    extern __shared__ float s[];
    float* Ct  = s + CT_OFF;
    float* R   = s + R_OFF;
    float* Gab = s + GAB_OFF;
    float* Msc = s + MS_OFF;
    float* WSs = s + WS_OFF;
    float* X   = s + X_OFF;

    const int tid  = threadIdx.x;
    const int lane = tid & 31;
    const int w    = tid >> 5;
    const int cp   = w >> 1;          // 0..9
    const int dg   = w & 1;           // 0..1
    const int c0   = 2 * cp;
    const int nc   = (cp == 9) ? 1 : 2;
    const int c1   = (nc == 2) ? c0 + 1 : c0;
    const int g    = gridDim.x;

    const float TWO_PI = 6.28318530717958647692f;

    // ---- once per CTA: cos table + prescaled M ----
    for (int e = tid; e < O * MM * MM; e += NT) {
        int n = e >> 10;
        int r = e & 1023;
        int i = r >> 5;
        int j = r & 31;
        float per = (float)(i * MM + j + 2);
        Ct[n * CT_STRIDE + i * ROWP + j] = cosf(TWO_PI * (float)n / per);
    }
    for (int e = tid; e < MM * MM; e += NT) {
        Msc[(e >> 5) * ROWP + (e & 31)] = Mw[e] * 0.0625f;
    }

    float* wsp = WSs + w * 32;

    for (int item = blockIdx.x; item < NITEMS; item += g) {
        const int ab = item >> 1;
        const int dh = item & 1;
        const int A = ab / O;
        const int B = ab % O;
        const int dstart = dh ? 10 : 0;
        const int dnum   = dh ? 9 : 10;

        __syncthreads();   // previous item fully consumed R/X/Gab

        // ---- R = 2x2 (a,b) pair-sum; batched MLP-10 loads (3200 float4, 5/thread) ----
        {
            const int strideB = DM * DM * MM;        // 12800 floats
            const int strideA = DM * strideB;
            const float4* H00 = (const float4*)(H + (long)A * strideA + (long)B * strideB);
            const float4* H01 = H00 + strideB / 4;
            const float4* H10 = H00 + strideA / 4;
            const float4* H11 = H10 + strideB / 4;
            float4* R4 = (float4*)R;

            float4 pa[5], pb[5], acc[5];
            // wave 1: 10 loads in flight
            #pragma unroll
            for (int k = 0; k < 5; k++) { pa[k] = H00[tid + k * NT]; pb[k] = H01[tid + k * NT]; }
            #pragma unroll
            for (int k = 0; k < 5; k++) {
                acc[k] = make_float4(pa[k].x + pb[k].x, pa[k].y + pb[k].y,
                                     pa[k].z + pb[k].z, pa[k].w + pb[k].w);
            }
            // wave 2: 10 loads in flight
            #pragma unroll
            for (int k = 0; k < 5; k++) { pa[k] = H10[tid + k * NT]; pb[k] = H11[tid + k * NT]; }
            #pragma unroll
            for (int k = 0; k < 5; k++) {
                R4[tid + k * NT] = make_float4(acc[k].x + pa[k].x + pb[k].x,
                                               acc[k].y + pa[k].y + pb[k].y,
                                               acc[k].z + pa[k].z + pb[k].z,
                                               acc[k].w + pa[k].w + pb[k].w);
            }
        }
        // ---- Gab = P * Ct[A] * Ct[B] (cooperative) ----
        for (int e = tid; e < MM * MM; e += NT) {
            int i = e >> 5, j = e & 31;
            Gab[i * ROWP + j] = P[e] * Ct[A * CT_STRIDE + i * ROWP + j]
                                     * Ct[B * CT_STRIDE + i * ROWP + j];
        }
        __syncthreads();   // R, Gab ready

        // ---- Phase P: all window-sums + matvecs -> X[c][dd][j] ----
        {
            ull Mreg[16];
            #pragma unroll
            for (int l4 = 0; l4 < 8; l4++) {
                ulonglong2 m = *reinterpret_cast<const ulonglong2*>(&Msc[lane * ROWP + 4 * l4]);
                Mreg[2 * l4] = m.x; Mreg[2 * l4 + 1] = m.y;
            }
            const int npairs = O * dnum;     // (c, dd) pairs
            #pragma unroll 1
            for (int p = w; p < npairs; p += 20) {
                const int c  = p / dnum;
                const int dd = p - c * dnum;
                const int d  = dstart + dd;
                float v = R[(c * DM + d) * MM + lane]
                        + R[(c * DM + d + 1) * MM + lane]
                        + R[((c + 1) * DM + d) * MM + lane]
                        + R[((c + 1) * DM + d + 1) * MM + lane];
                wsp[lane] = v;
                __syncwarp();
                ull a0 = 0, a1 = 0;
                #pragma unroll
                for (int l4 = 0; l4 < 8; l4++) {
                    ulonglong2 wv = *reinterpret_cast<const ulonglong2*>(&wsp[4 * l4]);
                    a0 = f2fma(Mreg[2 * l4],     wv.x, a0);
                    a1 = f2fma(Mreg[2 * l4 + 1], wv.y, a1);
                }
                X[(c * 10 + dd) * 32 + lane] = f2sum(a0) + f2sum(a1);
                __syncwarp();
            }
        }
        __syncthreads();   // X ready

        // ---- Phase C: warp = (c-pair, d-group), lane = i ----
        {
            // G = Gab * Ct[c] cached in registers
            ull G0[16], G1[16];
            #pragma unroll
            for (int l4 = 0; l4 < 8; l4++) {
                ulonglong2 gv = *reinterpret_cast<const ulonglong2*>(&Gab[lane * ROWP + 4 * l4]);
                ulonglong2 ca = *reinterpret_cast<const ulonglong2*>(&Ct[c0 * CT_STRIDE + lane * ROWP + 4 * l4]);
                ulonglong2 cb = *reinterpret_cast<const ulonglong2*>(&Ct[c1 * CT_STRIDE + lane * ROWP + 4 * l4]);
                G0[2 * l4]     = f2mul(gv.x, ca.x);
                G0[2 * l4 + 1] = f2mul(gv.y, ca.y);
                G1[2 * l4]     = f2mul(gv.x, cb.x);
                G1[2 * l4 + 1] = f2mul(gv.y, cb.y);
            }

            const int outBase = ab * (O * O) * MM;
            // this warp's dd list: dd = dg, dg+2, ... (< dnum); iterate rotated by cp
            const int cnt = (dnum - dg + 1) >> 1;
            int it0 = cp % cnt;            // stagger start across warps
            #pragma unroll 1
            for (int t = 0; t < cnt; t++) {
                int it = it0 + t; if (it >= cnt) it -= cnt;
                const int dd = dg + 2 * it;
                const int d  = dstart + dd;
                const float* cdrow = &Ct[d * CT_STRIDE + lane * ROWP];
                const float* xv0p  = &X[(c0 * 10 + dd) * 32];
                const float* xv1p  = &X[(c1 * 10 + dd) * 32];
                ull A0 = 0, A0b = 0, A1 = 0, A1b = 0;
                #pragma unroll
                for (int l4 = 0; l4 < 8; l4++) {
                    ulonglong2 cd  = *reinterpret_cast<const ulonglong2*>(cdrow + 4 * l4);
                    ulonglong2 xv0 = *reinterpret_cast<const ulonglong2*>(xv0p + 4 * l4);
                    ulonglong2 xv1 = *reinterpret_cast<const ulonglong2*>(xv1p + 4 * l4);
                    A0  = f2fma(f2mul(cd.x, G0[2 * l4]),     xv0.x, A0);
                    A0b = f2fma(f2mul(cd.y, G0[2 * l4 + 1]), xv0.y, A0b);
                    A1  = f2fma(f2mul(cd.x, G1[2 * l4]),     xv1.x, A1);
                    A1b = f2fma(f2mul(cd.y, G1[2 * l4 + 1]), xv1.y, A1b);
                }
                out[outBase + (c0 * O + d) * MM + lane] = f2sum(A0) + f2sum(A0b);
                if (nc == 2)
                    out[outBase + (c1 * O + d) * MM + lane] = f2sum(A1) + f2sum(A1b);
            }
        }
    }
}

extern "C" void kernel_launch(void* const* d_in, const int* in_sizes, int n_in,
                              void* d_out, int out_size)
{
    const float* H  = (const float*)d_in[0];
    const float* Mw = (const float*)d_in[1];
    const float* P  = (const float*)d_in[2];
    float* out = (float*)d_out;

    cudaFuncSetAttribute(pm4_kernel, cudaFuncAttributeMaxDynamicSharedMemorySize, SMEM_BYTES);

    int dev = 0, nsm = 148;
    cudaGetDevice(&dev);
    cudaDeviceGetAttribute(&nsm, cudaDevAttrMultiProcessorCount, dev);
    if (nsm <= 0) nsm = 148;
    int grid = nsm > NITEMS ? NITEMS : nsm;

    pm4_kernel<<<grid, NT, SMEM_BYTES>>>(H, Mw, P, out);
}